// round 12
// baseline (speedup 1.0000x reference)
#include <cuda_runtime.h>
#include <math.h>

// s = sum_i R[i] * ||Z[i,:]||^2 ; out = 1 - exp(-exp(s))
// Z: [N,128] fp32 row-major (256 MB), R: [N] fp32 (2 MB). HBM-bound reduction.
//
// Persistent single-wave grid + dynamic chunk stealing (SM-speed-adaptive, no
// static-partition tail). Deterministic: each 32KB chunk's partial sum goes to
// g_partials[chunk_id]; the final reduction is a fixed tree over chunk ids, so
// output bits are independent of which CTA processed which chunk.

#define NTHREADS   256
#define NBLOCKS    1184                 // 148x8; single resident wave at 32 regs
#define CHUNK4     2048                 // float4 per chunk = 32 KB
#define MAXCHUNKS  8192                 // 500000*32/2048 = 7813 < 8192

static __device__ float        g_partials[MAXCHUNKS];
static __device__ unsigned int g_next   = 0;   // chunk grab counter (wraps -> 0)
static __device__ unsigned int g_arrive = 0;   // finalize counter   (wraps -> 0)

__global__ __launch_bounds__(NTHREADS, 8) void bp_fused_kernel(
    const float* __restrict__ Z, const float* __restrict__ R, int nrows,
    float* __restrict__ out)
{
    const float4* __restrict__ Z4 = reinterpret_cast<const float4*>(Z);
    const int total4      = nrows * 32;                       // 32 float4 per row
    const int nchunks     = (total4 + CHUNK4 - 1) / CHUNK4;
    const unsigned total_grabs = (unsigned)nchunks + gridDim.x; // exact grabs/launch

    __shared__ unsigned s_chunk;
    __shared__ float    s_warp[NTHREADS / 32];

    if (threadIdx.x == 0)
        s_chunk = atomicInc(&g_next, total_grabs - 1);        // wraps to 0 at end
    __syncthreads();
    unsigned chunk = s_chunk;

    while (chunk < (unsigned)nchunks) {
        // Prefetch next chunk id; ATOMG latency overlaps with this chunk's loads.
        if (threadIdx.x == 0)
            s_chunk = atomicInc(&g_next, total_grabs - 1);

        const int base = (int)chunk * CHUNK4;
        float a0 = 0.f, a1 = 0.f, a2 = 0.f, a3 = 0.f;

        #pragma unroll
        for (int k = 0; k < CHUNK4 / (4 * NTHREADS); k++) {   // 2 groups of 4 loads
            int j0 = base + k * 4 * NTHREADS + threadIdx.x;
            int j1 = j0 + NTHREADS;
            int j2 = j0 + 2 * NTHREADS;
            int j3 = j0 + 3 * NTHREADS;
            if (j3 < total4) {                                // full-chunk fast path
                float4 v0 = __ldcs(&Z4[j0]);
                float4 v1 = __ldcs(&Z4[j1]);
                float4 v2 = __ldcs(&Z4[j2]);
                float4 v3 = __ldcs(&Z4[j3]);
                float  r0 = __ldg(&R[j0 >> 5]);
                float  r1 = __ldg(&R[j1 >> 5]);
                float  r2 = __ldg(&R[j2 >> 5]);
                float  r3 = __ldg(&R[j3 >> 5]);
                a0 = fmaf(v0.x*v0.x + v0.y*v0.y + v0.z*v0.z + v0.w*v0.w, r0, a0);
                a1 = fmaf(v1.x*v1.x + v1.y*v1.y + v1.z*v1.z + v1.w*v1.w, r1, a1);
                a2 = fmaf(v2.x*v2.x + v2.y*v2.y + v2.z*v2.z + v2.w*v2.w, r2, a2);
                a3 = fmaf(v3.x*v3.x + v3.y*v3.y + v3.z*v3.z + v3.w*v3.w, r3, a3);
            } else {                                          // tail chunk
                if (j0 < total4) {
                    float4 v = __ldcs(&Z4[j0]);
                    a0 = fmaf(v.x*v.x + v.y*v.y + v.z*v.z + v.w*v.w,
                              __ldg(&R[j0 >> 5]), a0);
                }
                if (j1 < total4) {
                    float4 v = __ldcs(&Z4[j1]);
                    a1 = fmaf(v.x*v.x + v.y*v.y + v.z*v.z + v.w*v.w,
                              __ldg(&R[j1 >> 5]), a1);
                }
                if (j2 < total4) {
                    float4 v = __ldcs(&Z4[j2]);
                    a2 = fmaf(v.x*v.x + v.y*v.y + v.z*v.z + v.w*v.w,
                              __ldg(&R[j2 >> 5]), a2);
                }
            }
        }

        float acc = (a0 + a1) + (a2 + a3);
        #pragma unroll
        for (int o = 16; o > 0; o >>= 1)
            acc += __shfl_xor_sync(0xffffffffu, acc, o);
        if ((threadIdx.x & 31) == 0) s_warp[threadIdx.x >> 5] = acc;
        __syncthreads();                                      // warp sums ready

        if (threadIdx.x == 0) {
            float bsum = 0.f;
            #pragma unroll
            for (int w = 0; w < NTHREADS / 32; w++) bsum += s_warp[w];
            g_partials[chunk] = bsum;
        }
        __syncthreads();          // all threads done with s_warp AND s_chunk is
        chunk = s_chunk;          // safe to read (thread0's atomic retired)
    }

    // ---- last block finalizes: fixed tree over chunk ids => deterministic ----
    __shared__ bool is_last;
    __threadfence();
    if (threadIdx.x == 0) {
        unsigned prev = atomicInc(&g_arrive, gridDim.x - 1); // wraps -> auto-reset
        is_last = (prev == gridDim.x - 1);
    }
    __syncthreads();
    if (!is_last) return;

    double dacc = 0.0;
    for (int i = threadIdx.x; i < nchunks; i += NTHREADS)
        dacc += (double)g_partials[i];

    #pragma unroll
    for (int o = 16; o > 0; o >>= 1)
        dacc += __shfl_xor_sync(0xffffffffu, dacc, o);

    __shared__ double dsmem[NTHREADS / 32];
    if ((threadIdx.x & 31) == 0) dsmem[threadIdx.x >> 5] = dacc;
    __syncthreads();

    if (threadIdx.x == 0) {
        double s = 0.0;
        #pragma unroll
        for (int w = 0; w < NTHREADS / 32; w++) s += dsmem[w];
        double lam = exp(s);
        out[0] = (float)(1.0 - exp(-lam));
    }
}

extern "C" void kernel_launch(void* const* d_in, const int* in_sizes, int n_in,
                              void* d_out, int out_size)
{
    const float* a0 = (const float*)d_in[0];
    const float* a1 = (const float*)d_in[1];
    const float* Z; const float* R; int nrows;
    if (in_sizes[0] >= in_sizes[1]) { Z = a0; R = a1; nrows = in_sizes[1]; }
    else                            { Z = a1; R = a0; nrows = in_sizes[0]; }

    bp_fused_kernel<<<NBLOCKS, NTHREADS>>>(Z, R, nrows, (float*)d_out);
}